// round 14
// baseline (speedup 1.0000x reference)
#include <cuda_runtime.h>

#define BATCH 256
typedef unsigned long long u64;

// ---------------- intermediate scratch (device globals; no allocs) ----------
// h1..h4 are batch-PAIR-interleaved: u64 element = (b_even, b_odd) floats.
__device__ u64 g_h1[(BATCH/2)*3*15*15*15*15];
__device__ u64 g_h2[(BATCH/2)*3*12*12*12*12];
__device__ u64 g_h3[(BATCH/2)*4*9*9*9*9];
__device__ u64 g_h4[(BATCH/2)*5*6*6*6*6];

__device__ __forceinline__ u64 pk2(float lo, float hi) {
    u64 d; asm("mov.b64 %0, {%1, %2};" : "=l"(d) : "f"(lo), "f"(hi)); return d;
}
__device__ __forceinline__ void unpk2(u64 v, float& lo, float& hi) {
    asm("mov.b64 {%0, %1}, %2;" : "=f"(lo), "=f"(hi) : "l"(v));
}
__device__ __forceinline__ u64 fma2(u64 a, u64 b, u64 c) {
    u64 d; asm("fma.rn.f32x2 %0, %1, %2, %3;" : "=l"(d) : "l"(a), "l"(b), "l"(c));
    return d;
}
__device__ __forceinline__ u64 relu2(u64 v) {
    float lo, hi; unpk2(v, lo, hi);
    return pk2(fmaxf(lo, 0.f), fmaxf(hi, 0.f));
}
// Broadcast-hoist NW u64 weights via LDS.128 (NW even, 16B-aligned src).
template<int NW>
__device__ __forceinline__ void hoistw(u64* wr, const u64* src) {
    const ulonglong2* p = reinterpret_cast<const ulonglong2*>(src);
    #pragma unroll
    for (int i = 0; i < NW / 2; i++) { ulonglong2 v = p[i]; wr[2*i] = v.x; wr[2*i+1] = v.y; }
}

// ---------------------------------------------------------------------------
// L1: planar float input, pair-interleaved u64 output. ROLLING row window:
// only TY+1 rows resident; prefetch row ky+TY before ky's fma block.
// ---------------------------------------------------------------------------
template<int CIN,int COUT,int S,int K,int TY,int TZ,int SLAB,int BDIM,int MINB>
__global__ __launch_bounds__(BDIM, MINB)
void conv4d_l1(const float* __restrict__ in, const float* __restrict__ wt,
               const float* __restrict__ bias, u64* __restrict__ out)
{
    constexpr int O   = S - K + 1;
    static_assert(O % TY == 0 && O % TZ == 0 && BDIM >= O * O, "");
    constexpr int NTY = O / TY, NTZ = O / TZ;
    constexpr int TYI = TY + K - 1, TZI = TZ + K - 1;
    static_assert(SLAB >= TYI * TZI && SLAB % 2 == 1, "");
    constexpr int K4  = K * K * K * K;
    constexpr int NR  = TY + 1;               // resident rows
    constexpr int ISZ = S * S * SLAB;
    constexpr int WCH = COUT * K4;
    static_assert((K * COUT) % 2 == 0, "");

    extern __shared__ u64 smu[];
    u64* sw2 = smu;
    u64* siu = smu + WCH;

    const int tid = threadIdx.x;
    int bid = blockIdx.x;
    const int tzb = bid % NTZ; bid /= NTZ;
    const int tyb = bid % NTY;
    const int bp  = bid / NTY;
    const int y0 = tyb * TY, z0 = tzb * TZ;

    const int pos = tid;
    const int ow  = pos / O, ox = pos - ow * O;
    const bool active = (pos < O * O);

    u64 acc[COUT][TY][TZ];
    #pragma unroll
    for (int c = 0; c < COUT; c++) {
        float bv = bias[c];
        u64 bpk = pk2(bv, bv);
        #pragma unroll
        for (int ty = 0; ty < TY; ty++)
            #pragma unroll
            for (int tz = 0; tz < TZ; tz++) acc[c][ty][tz] = bpk;
    }

    const float* inb0 = in + (size_t)(2*bp)     * CIN * S * S * S * S;
    const float* inb1 = in + (size_t)(2*bp + 1) * CIN * S * S * S * S;

    for (int cin = 0; cin < CIN; cin++) {
        __syncthreads();
        for (int i = tid; i < WCH; i += BDIM) {
            int c = i / K4, r = i - c * K4;
            float w = wt[(c * CIN + cin) * K4 + r];
            sw2[r * COUT + c] = pk2(w, w);
        }
        for (int i = tid; i < ISZ; i += BDIM) {
            int s = i % SLAB; int t = i / SLAB;
            int xx = t % S;   int ww = t / S;
            float v0 = 0.f, v1 = 0.f;
            if (s < TYI * TZI) {
                int iy = s / TZI, zz = s - iy * TZI;
                size_t gidx = ((((size_t)cin * S + ww) * S + xx) * S + (y0 + iy)) * S
                              + (z0 + zz);
                v0 = inb0[gidx]; v1 = inb1[gidx];
            }
            siu[i] = pk2(v0, v1);
        }
        __syncthreads();

        if (active) {
            #pragma unroll 1
            for (int kw = 0; kw < K; kw++)
            #pragma unroll 1
            for (int kx = 0; kx < K; kx++) {
                const u64* ip = siu + ((ow + kw) * S + ox + kx) * SLAB;
                u64 rows[NR][TZI];
                #pragma unroll
                for (int r = 0; r < TY; r++)
                    #pragma unroll
                    for (int z = 0; z < TZI; z++) rows[r][z] = ip[r * TZI + z];

                const u64* wb = sw2 + ((kw * K + kx) * K * K) * COUT;
                #pragma unroll
                for (int ky = 0; ky < K; ky++) {
                    if (ky < K - 1) {                     // prefetch row ky+TY
                        const int rr = ky + TY, slot = rr % NR;
                        #pragma unroll
                        for (int z = 0; z < TZI; z++) rows[slot][z] = ip[rr * TZI + z];
                    }
                    u64 wr[K * COUT];
                    hoistw<K * COUT>(wr, wb + ky * K * COUT);
                    #pragma unroll
                    for (int ty = 0; ty < TY; ty++) {
                        const int sl = (ky + ty) % NR;
                        #pragma unroll
                        for (int kz = 0; kz < K; kz++)
                        #pragma unroll
                        for (int tz = 0; tz < TZ; tz++)
                        #pragma unroll
                        for (int c = 0; c < COUT; c++)
                            acc[c][ty][tz] = fma2(rows[sl][tz + kz],
                                                  wr[kz*COUT + c], acc[c][ty][tz]);
                    }
                }
            }
        }
    }

    if (active) {
        #pragma unroll
        for (int c = 0; c < COUT; c++)
        #pragma unroll
        for (int ty = 0; ty < TY; ty++)
        #pragma unroll
        for (int tz = 0; tz < TZ; tz++) {
            size_t idx = (((((size_t)bp * COUT + c) * O + ow) * O + ox) * O
                          + (y0 + ty)) * O + (z0 + tz);
            out[idx] = relu2(acc[c][ty][tz]);
        }
    }
}

// ---------------------------------------------------------------------------
// Rolling-row pair conv (L2, L3). u64 in / u64 out.
// ---------------------------------------------------------------------------
template<int CIN,int COUT,int S,int K,int TY,int TZ,int SLAB,int BDIM,int MINB>
__global__ __launch_bounds__(BDIM, MINB)
void conv4d_roll_u(const u64* __restrict__ in, const float* __restrict__ wt,
                   const float* __restrict__ bias, u64* __restrict__ out)
{
    constexpr int O   = S - K + 1;
    static_assert(O % TY == 0 && O % TZ == 0 && BDIM >= O * O, "");
    constexpr int NTY = O / TY, NTZ = O / TZ;
    constexpr int TYI = TY + K - 1, TZI = TZ + K - 1;
    static_assert(SLAB >= TYI * TZI && SLAB % 2 == 1, "");
    constexpr int K4  = K * K * K * K;
    constexpr int NR  = TY + 1;
    constexpr int ISZ = S * S * SLAB;
    constexpr int WCH = COUT * K4;
    static_assert((K * COUT) % 2 == 0, "");

    extern __shared__ u64 smu[];
    u64* sw2 = smu;
    u64* siu = smu + WCH;

    const int tid = threadIdx.x;
    int bid = blockIdx.x;
    const int tzb = bid % NTZ; bid /= NTZ;
    const int tyb = bid % NTY;
    const int bp  = bid / NTY;
    const int y0 = tyb * TY, z0 = tzb * TZ;

    const int pos = tid;
    const int ow  = pos / O, ox = pos - ow * O;
    const bool active = (pos < O * O);

    u64 acc[COUT][TY][TZ];
    #pragma unroll
    for (int c = 0; c < COUT; c++) {
        float bv = bias[c];
        u64 bpk = pk2(bv, bv);
        #pragma unroll
        for (int ty = 0; ty < TY; ty++)
            #pragma unroll
            for (int tz = 0; tz < TZ; tz++) acc[c][ty][tz] = bpk;
    }

    const u64* inb = in + (size_t)bp * CIN * S * S * S * S;

    for (int cin = 0; cin < CIN; cin++) {
        __syncthreads();
        for (int i = tid; i < WCH; i += BDIM) {
            int c = i / K4, r = i - c * K4;
            float w = wt[(c * CIN + cin) * K4 + r];
            sw2[r * COUT + c] = pk2(w, w);
        }
        for (int i = tid; i < ISZ; i += BDIM) {
            int s = i % SLAB; int t = i / SLAB;
            int xx = t % S;   int ww = t / S;
            u64 v = 0;
            if (s < TYI * TZI) {
                int iy = s / TZI, zz = s - iy * TZI;
                v = inb[((((size_t)cin * S + ww) * S + xx) * S + (y0 + iy)) * S
                        + (z0 + zz)];
            }
            siu[i] = v;
        }
        __syncthreads();

        if (active) {
            #pragma unroll 1
            for (int kw = 0; kw < K; kw++)
            #pragma unroll 1
            for (int kx = 0; kx < K; kx++) {
                const u64* ip = siu + ((ow + kw) * S + ox + kx) * SLAB;
                u64 rows[NR][TZI];
                #pragma unroll
                for (int r = 0; r < TY; r++)
                    #pragma unroll
                    for (int z = 0; z < TZI; z++) rows[r][z] = ip[r * TZI + z];

                const u64* wb = sw2 + ((kw * K + kx) * K * K) * COUT;
                #pragma unroll
                for (int ky = 0; ky < K; ky++) {
                    if (ky < K - 1) {
                        const int rr = ky + TY, slot = rr % NR;
                        #pragma unroll
                        for (int z = 0; z < TZI; z++) rows[slot][z] = ip[rr * TZI + z];
                    }
                    u64 wr[K * COUT];
                    hoistw<K * COUT>(wr, wb + ky * K * COUT);
                    #pragma unroll
                    for (int ty = 0; ty < TY; ty++) {
                        const int sl = (ky + ty) % NR;
                        #pragma unroll
                        for (int kz = 0; kz < K; kz++)
                        #pragma unroll
                        for (int tz = 0; tz < TZ; tz++)
                        #pragma unroll
                        for (int c = 0; c < COUT; c++)
                            acc[c][ty][tz] = fma2(rows[sl][tz + kz],
                                                  wr[kz*COUT + c], acc[c][ty][tz]);
                    }
                }
            }
        }
    }

    if (active) {
        #pragma unroll
        for (int c = 0; c < COUT; c++)
        #pragma unroll
        for (int ty = 0; ty < TY; ty++)
        #pragma unroll
        for (int tz = 0; tz < TZ; tz++) {
            size_t idx = (((((size_t)bp * COUT + c) * O + ow) * O + ox) * O
                          + (y0 + ty)) * O + (z0 + tz);
            out[idx] = relu2(acc[c][ty][tz]);
        }
    }
}

// ---------------------------------------------------------------------------
// L4: whole-spatial pair conv, W-split, rolling 2-row pipeline.
// ---------------------------------------------------------------------------
template<int CIN,int COUT,int S,int K,int WSPLIT,int BDIM,int MINB>
__global__ __launch_bounds__(BDIM, MINB)
void conv4d_fullz_u(const u64* __restrict__ in, const float* __restrict__ wt,
                    const float* __restrict__ bias, u64* __restrict__ out)
{
    constexpr int O    = S - K + 1;
    constexpr int K4   = K * K * K * K;
    constexpr int OWT  = O / WSPLIT;
    constexpr int WT   = OWT + K - 1;
    static_assert(O % WSPLIT == 0 && BDIM >= OWT * O * O, "");
    constexpr int ISZ = WT * S * S * S;
    constexpr int WCH = COUT * K4;
    static_assert((K * COUT) % 2 == 0, "");

    extern __shared__ u64 smu[];
    u64* sw2 = smu;
    u64* siu = smu + WCH;

    const int tid = threadIdx.x;
    const int ws  = blockIdx.x % WSPLIT;
    const int bp  = blockIdx.x / WSPLIT;
    const int w0  = ws * OWT;

    const int pos = tid;
    int oy = pos % O, t0 = pos / O;
    int ox = t0 % O, owl = t0 / O;
    const bool active = (pos < OWT * O * O);

    u64 acc[COUT][O];
    #pragma unroll
    for (int c = 0; c < COUT; c++) {
        float bv = bias[c];
        u64 bpk = pk2(bv, bv);
        #pragma unroll
        for (int z = 0; z < O; z++) acc[c][z] = bpk;
    }

    const u64* inb = in + (size_t)bp * CIN * S * S * S * S;

    for (int cin = 0; cin < CIN; cin++) {
        __syncthreads();
        for (int i = tid; i < WCH; i += BDIM) {
            int c = i / K4, r = i - c * K4;
            float w = wt[(c * CIN + cin) * K4 + r];
            sw2[r * COUT + c] = pk2(w, w);
        }
        for (int i = tid; i < ISZ; i += BDIM) {
            int zz = i % S; int t = i / S;
            int yy = t % S; t /= S;
            int xx = t % S; int wl = t / S;
            siu[i] = inb[((((size_t)cin * S + (w0 + wl)) * S + xx) * S + yy) * S + zz];
        }
        __syncthreads();

        if (active) {
            #pragma unroll 1
            for (int kw = 0; kw < K; kw++)
            #pragma unroll 1
            for (int kx = 0; kx < K; kx++) {
                const u64* plane = siu + ((owl + kw) * S + ox + kx) * S * S;
                u64 rows[2][S];
                #pragma unroll
                for (int z = 0; z < S; z++) rows[0][z] = plane[oy * S + z];

                const u64* wb = sw2 + ((kw * K + kx) * K * K) * COUT;
                #pragma unroll
                for (int ky = 0; ky < K; ky++) {
                    if (ky < K - 1) {
                        const int slot = (ky + 1) & 1;
                        #pragma unroll
                        for (int z = 0; z < S; z++)
                            rows[slot][z] = plane[(oy + ky + 1) * S + z];
                    }
                    u64 wr[K * COUT];
                    hoistw<K * COUT>(wr, wb + ky * K * COUT);
                    const int sl = ky & 1;
                    #pragma unroll
                    for (int kz = 0; kz < K; kz++)
                    #pragma unroll
                    for (int z = 0; z < O; z++)
                    #pragma unroll
                    for (int c = 0; c < COUT; c++)
                        acc[c][z] = fma2(rows[sl][z + kz], wr[kz*COUT + c], acc[c][z]);
                }
            }
        }
    }

    if (active) {
        const int ow = w0 + owl;
        #pragma unroll
        for (int c = 0; c < COUT; c++)
        #pragma unroll
        for (int z = 0; z < O; z++) {
            size_t idx = (((((size_t)bp * COUT + c) * O + ow) * O + ox) * O + oy) * O + z;
            out[idx] = relu2(acc[c][z]);
        }
    }
}

// ---------------------------------------------------------------------------
// FUSED L5 + dense head. One block per batch pair. (unchanged)
// ---------------------------------------------------------------------------
template<int CIN,int COUT,int S,int K,int BDIM>
__global__ __launch_bounds__(BDIM)
void conv5_head_u(const u64* __restrict__ in, const float* __restrict__ wt,
                  const float* __restrict__ bias,
                  const float* __restrict__ dw1, const float* __restrict__ db1,
                  const float* __restrict__ dw2, const float* __restrict__ db2,
                  float* __restrict__ out)
{
    constexpr int O    = S - K + 1;            // 4
    constexpr int K4   = K * K * K * K;
    constexpr int ISZ  = CIN * S * S * S * S;  // 6480 u64
    constexpr int WSZ  = COUT * CIN * K4;      // 2025 u64
    constexpr int FEAT = COUT * O * O * O * O; // 1280
    static_assert(BDIM >= FEAT / COUT, "");

    extern __shared__ u64 smu[];
    u64*   siu   = smu;
    u64*   sw2   = smu + ISZ;
    float* srow0 = (float*)(smu + ISZ + WSZ);
    float* srow1 = srow0 + FEAT;
    float* gbuf  = srow1 + FEAT;

    const int tid = threadIdx.x, bp = blockIdx.x;

    for (int i = tid; i < WSZ; i += BDIM) {
        int c = i / (CIN*K4); int r = i - c * (CIN*K4);
        float w = wt[i];
        sw2[r * COUT + c] = pk2(w, w);
    }
    const u64* inb = in + (size_t)bp * ISZ;
    for (int i = tid; i < ISZ; i += BDIM) siu[i] = inb[i];
    __syncthreads();

    {
        const int pos = tid;
        if (pos < O * O * O * O) {
            int oz = pos % O; int t = pos / O;
            int oy = t % O;   t /= O;
            int ox = t % O;   int ow = t / O;

            u64 acc[COUT];
            #pragma unroll
            for (int c = 0; c < COUT; c++) { float bv = bias[c]; acc[c] = pk2(bv, bv); }

            #pragma unroll 1
            for (int cin = 0; cin < CIN; cin++)
            #pragma unroll 1
            for (int kw = 0; kw < K; kw++)
            #pragma unroll 1
            for (int kx = 0; kx < K; kx++) {
                const u64* plane = siu + ((cin * S + ow + kw) * S + ox + kx) * S * S;
                #pragma unroll
                for (int ky = 0; ky < K; ky++) {
                    const u64* r  = plane + (oy + ky) * S + oz;
                    const u64* wp = sw2 + ((((cin*K + kw)*K + kx)*K + ky) * K) * COUT;
                    #pragma unroll
                    for (int kz = 0; kz < K; kz++)
                    #pragma unroll
                    for (int c = 0; c < COUT; c++)
                        acc[c] = fma2(r[kz], wp[kz * COUT + c], acc[c]);
                }
            }
            #pragma unroll
            for (int c = 0; c < COUT; c++) {
                float lo, hi; unpk2(acc[c], lo, hi);
                int fidx = c * (O*O*O*O) + pos;
                srow0[fidx] = fmaxf(lo, 0.f);
                srow1[fidx] = fmaxf(hi, 0.f);
            }
        }
    }
    __syncthreads();

    const int f = tid >> 2, p = tid & 3;
    #pragma unroll
    for (int r = 0; r < 2; r++) {
        const float* srow = r ? srow1 : srow0;
        float s = 0.f;
        if (f < 33) {
            const float* wrow = dw1 + f * FEAT;
            for (int k = p; k < FEAT; k += 4) s = fmaf(srow[k], wrow[k], s);
        }
        s += __shfl_xor_sync(0xffffffffu, s, 1);
        s += __shfl_xor_sync(0xffffffffu, s, 2);
        if (p == 0 && f < 33) gbuf[r * 33 + f] = fmaxf(s + db1[f], 0.f);
    }
    __syncthreads();

    if (tid < 2) {
        const float* g = gbuf + tid * 33;
        float l0 = db2[0], l1 = db2[1];
        #pragma unroll
        for (int j = 0; j < 33; j++) {
            l0 = fmaf(g[j], dw2[j], l0);
            l1 = fmaf(g[j], dw2[33 + j], l1);
        }
        float m  = fmaxf(l0, l1);
        float e0 = expf(l0 - m), e1 = expf(l1 - m);
        float inv = 1.f / (e0 + e1);
        out[(2*bp + tid) * 2 + 0] = e0 * inv;
        out[(2*bp + tid) * 2 + 1] = e1 * inv;
    }
}

// ---------------------------------------------------------------------------
extern "C" void kernel_launch(void* const* d_in, const int* in_sizes, int n_in,
                              void* d_out, int out_size)
{
    (void)in_sizes; (void)n_in; (void)out_size;
    const float* x   = (const float*)d_in[0];
    const float* w1  = (const float*)d_in[1];  const float* b1  = (const float*)d_in[2];
    const float* w2  = (const float*)d_in[3];  const float* b2  = (const float*)d_in[4];
    const float* w3  = (const float*)d_in[5];  const float* b3  = (const float*)d_in[6];
    const float* w4  = (const float*)d_in[7];  const float* b4  = (const float*)d_in[8];
    const float* w5  = (const float*)d_in[9];  const float* b5  = (const float*)d_in[10];
    const float* dw1 = (const float*)d_in[11]; const float* db1 = (const float*)d_in[12];
    const float* dw2 = (const float*)d_in[13]; const float* db2 = (const float*)d_in[14];
    float* out = (float*)d_out;

    void *p1, *p2, *p3, *p4;
    cudaGetSymbolAddress(&p1, g_h1);
    cudaGetSymbolAddress(&p2, g_h2);
    cudaGetSymbolAddress(&p3, g_h3);
    cudaGetSymbolAddress(&p4, g_h4);
    u64 *h1 = (u64*)p1, *h2 = (u64*)p2, *h3 = (u64*)p3, *h4 = (u64*)p4;

    constexpr int SM1 = (3*256 + 18*18*37) * 8;   // 102,048
    constexpr int SM2 = (3*256 + 15*15*35) * 8;   //  69,144 -> 3 CTAs (regs now fit)
    constexpr int SM3 = (4*256 + 12*12*37) * 8;   //  50,816 -> 4 CTAs
    constexpr int SM4 = (5*256 + 6*9*9*9)  * 8;   //  45,232
    constexpr int SM5 = (6480 + 2025) * 8 + (2*1280 + 68) * 4;  // ~78.6 KB

    cudaFuncSetAttribute((const void*)conv4d_l1<1,3,18,4,3,3,37,256,2>,
                         cudaFuncAttributeMaxDynamicSharedMemorySize, SM1);
    cudaFuncSetAttribute((const void*)conv4d_roll_u<3,3,15,4,2,4,35,160,3>,
                         cudaFuncAttributeMaxDynamicSharedMemorySize, SM2);
    cudaFuncSetAttribute((const void*)conv4d_roll_u<3,4,12,4,3,3,37,96,4>,
                         cudaFuncAttributeMaxDynamicSharedMemorySize, SM3);
    cudaFuncSetAttribute((const void*)conv4d_fullz_u<4,5,9,4,2,128,3>,
                         cudaFuncAttributeMaxDynamicSharedMemorySize, SM4);
    cudaFuncSetAttribute((const void*)conv5_head_u<5,5,6,3,256>,
                         cudaFuncAttributeMaxDynamicSharedMemorySize, SM5);

    constexpr int NBP = BATCH / 2;   // 128 batch pairs

    conv4d_l1<1,3,18,4,3,3,37,256,2><<<NBP*5*5, 256, SM1>>>(x,  w1, b1, h1);
    conv4d_roll_u<3,3,15,4,2,4,35,160,3><<<NBP*6*3, 160, SM2>>>(h1, w2, b2, h2);
    conv4d_roll_u<3,4,12,4,3,3,37,96,4><<<NBP*3*3,  96, SM3>>>(h2, w3, b3, h3);
    conv4d_fullz_u<4,5,9,4,2,128,3><<<NBP*2, 128, SM4>>>(h3, w4, b4, h4);
    conv5_head_u<5,5,6,3,256><<<NBP, 256, SM5>>>(h4, w5, b5,
                                                 dw1, db1, dw2, db2, out);
}

// round 15
// speedup vs baseline: 1.2085x; 1.2085x over previous
#include <cuda_runtime.h>

#define BATCH 256
typedef unsigned long long u64;

// ---------------- intermediate scratch (device globals; no allocs) ----------
// h1..h4 are batch-PAIR-interleaved: u64 element = (b_even, b_odd) floats.
__device__ u64 g_h1[(BATCH/2)*3*15*15*15*15];
__device__ u64 g_h2[(BATCH/2)*3*12*12*12*12];
__device__ u64 g_h3[(BATCH/2)*4*9*9*9*9];
__device__ u64 g_h4[(BATCH/2)*5*6*6*6*6];

__device__ __forceinline__ u64 pk2(float lo, float hi) {
    u64 d; asm("mov.b64 %0, {%1, %2};" : "=l"(d) : "f"(lo), "f"(hi)); return d;
}
__device__ __forceinline__ void unpk2(u64 v, float& lo, float& hi) {
    asm("mov.b64 {%0, %1}, %2;" : "=f"(lo), "=f"(hi) : "l"(v));
}
__device__ __forceinline__ u64 fma2(u64 a, u64 b, u64 c) {
    u64 d; asm("fma.rn.f32x2 %0, %1, %2, %3;" : "=l"(d) : "l"(a), "l"(b), "l"(c));
    return d;
}
__device__ __forceinline__ u64 relu2(u64 v) {
    float lo, hi; unpk2(v, lo, hi);
    return pk2(fmaxf(lo, 0.f), fmaxf(hi, 0.f));
}
// Broadcast-hoist NW u64 weights via LDS.128 (NW even, 16B-aligned src).
template<int NW>
__device__ __forceinline__ void hoistw(u64* wr, const u64* src) {
    const ulonglong2* p = reinterpret_cast<const ulonglong2*>(src);
    #pragma unroll
    for (int i = 0; i < NW / 2; i++) { ulonglong2 v = p[i]; wr[2*i] = v.x; wr[2*i+1] = v.y; }
}

// ---------------------------------------------------------------------------
// L1: planar float input, pair-interleaved u64 output. Plane-walk staging:
// lane window coords decomposed ONCE; per-cin copy uses running pointers.
// ---------------------------------------------------------------------------
template<int CIN,int COUT,int S,int K,int TY,int TZ,int SLAB,int BDIM,int MINB>
__global__ __launch_bounds__(BDIM, MINB)
void conv4d_l1(const float* __restrict__ in, const float* __restrict__ wt,
               const float* __restrict__ bias, u64* __restrict__ out)
{
    constexpr int O   = S - K + 1;
    static_assert(O % TY == 0 && O % TZ == 0 && BDIM >= O * O, "");
    constexpr int NTY = O / TY, NTZ = O / TZ;
    constexpr int TYI = TY + K - 1, TZI = TZ + K - 1;
    constexpr int WIN = TYI * TZI;
    static_assert(SLAB >= WIN && SLAB % 2 == 1 && WIN <= 64, "");
    constexpr int K4  = K * K * K * K;
    constexpr int S2  = S * S;
    constexpr int S4  = S2 * S2;
    constexpr int NWARP = BDIM / 32;
    constexpr int WCH = COUT * K4;
    static_assert((K * COUT) % 2 == 0, "");

    extern __shared__ u64 smu[];
    u64* sw2 = smu;
    u64* siu = smu + WCH;

    const int tid  = threadIdx.x;
    const int lane = tid & 31, wrp = tid >> 5;
    int bid = blockIdx.x;
    const int tzb = bid % NTZ; bid /= NTZ;
    const int tyb = bid % NTY;
    const int bp  = bid / NTY;
    const int y0 = tyb * TY, z0 = tzb * TZ;

    // staging geometry (computed once)
    const int iy1 = lane / TZI, zz1 = lane - iy1 * TZI;
    const int l2  = lane + 32;
    const int iy2 = l2 / TZI,   zz2 = l2 - iy2 * TZI;
    const bool e1 = lane < WIN, e2 = l2 < WIN;
    const int soff1 = (y0 + iy1) * S + z0 + zz1;
    const int soff2 = (iy2 - iy1) * S + (zz2 - zz1);   // src delta elem1->elem2

    const int pos = tid;
    const int ow  = pos / O, ox = pos - ow * O;
    const bool active = (pos < O * O);

    u64 acc[COUT][TY][TZ];
    #pragma unroll
    for (int c = 0; c < COUT; c++) {
        float bv = bias[c];
        u64 bpk = pk2(bv, bv);
        #pragma unroll
        for (int ty = 0; ty < TY; ty++)
            #pragma unroll
            for (int tz = 0; tz < TZ; tz++) acc[c][ty][tz] = bpk;
    }

    const float* inb0 = in + (size_t)(2*bp)     * CIN * S4;
    const float* inb1 = in + (size_t)(2*bp + 1) * CIN * S4;

    for (int cin = 0; cin < CIN; cin++) {
        __syncthreads();
        for (int i = tid; i < WCH; i += BDIM) {
            int c = i / K4, r = i - c * K4;
            float w = wt[(c * CIN + cin) * K4 + r];
            sw2[r * COUT + c] = pk2(w, w);
        }
        {
            const float* a = inb0 + (size_t)cin * S4 + soff1 + wrp * S2;
            const float* b = inb1 + (size_t)cin * S4 + soff1 + wrp * S2;
            u64* d = siu + iy1 * TZI + zz1 + wrp * SLAB;
            for (int p = wrp; p < S2; p += NWARP) {
                if (e1) d[0]  = pk2(a[0], b[0]);
                if (e2) d[32] = pk2(a[soff2], b[soff2]);
                a += NWARP * S2; b += NWARP * S2; d += NWARP * SLAB;
            }
        }
        __syncthreads();

        if (active) {
            #pragma unroll 1
            for (int kw = 0; kw < K; kw++)
            #pragma unroll 1
            for (int kx = 0; kx < K; kx++) {
                const u64* ip = siu + ((ow + kw) * S + ox + kx) * SLAB;
                const u64* wb = sw2 + ((kw * K + kx) * K * K) * COUT;
                #pragma unroll
                for (int ky = 0; ky < K; ky++) {
                    u64 wr[K * COUT];
                    hoistw<K * COUT>(wr, wb + ky * K * COUT);
                    #pragma unroll
                    for (int ty = 0; ty < TY; ty++) {
                        const u64* rp0 = ip + (ky + ty) * TZI;
                        u64 row[TZI];
                        #pragma unroll
                        for (int z = 0; z < TZI; z++) row[z] = rp0[z];
                        #pragma unroll
                        for (int kz = 0; kz < K; kz++)
                        #pragma unroll
                        for (int tz = 0; tz < TZ; tz++)
                        #pragma unroll
                        for (int c = 0; c < COUT; c++)
                            acc[c][ty][tz] = fma2(row[tz + kz], wr[kz*COUT + c],
                                                  acc[c][ty][tz]);
                    }
                }
            }
        }
    }

    if (active) {
        #pragma unroll
        for (int c = 0; c < COUT; c++)
        #pragma unroll
        for (int ty = 0; ty < TY; ty++)
        #pragma unroll
        for (int tz = 0; tz < TZ; tz++) {
            size_t idx = (((((size_t)bp * COUT + c) * O + ow) * O + ox) * O
                          + (y0 + ty)) * O + (z0 + tz);
            out[idx] = relu2(acc[c][ty][tz]);
        }
    }
}

// ---------------------------------------------------------------------------
// Window-resident pair conv (L2, L3). u64 in / u64 out. Plane-walk staging.
// ---------------------------------------------------------------------------
template<int CIN,int COUT,int S,int K,int TY,int TZ,int SLAB,int BDIM,int MINB>
__global__ __launch_bounds__(BDIM, MINB)
void conv4d_win_u(const u64* __restrict__ in, const float* __restrict__ wt,
                  const float* __restrict__ bias, u64* __restrict__ out)
{
    constexpr int O   = S - K + 1;
    static_assert(O % TY == 0 && O % TZ == 0 && BDIM >= O * O, "");
    constexpr int NTY = O / TY, NTZ = O / TZ;
    constexpr int TYI = TY + K - 1, TZI = TZ + K - 1;
    constexpr int WIN = TYI * TZI;
    static_assert(SLAB >= WIN && SLAB % 2 == 1 && WIN <= 64, "");
    constexpr int K4  = K * K * K * K;
    constexpr int S2  = S * S;
    constexpr int S4  = S2 * S2;
    constexpr int NWARP = BDIM / 32;
    constexpr int WCH = COUT * K4;
    static_assert((K * COUT) % 2 == 0, "");

    extern __shared__ u64 smu[];
    u64* sw2 = smu;
    u64* siu = smu + WCH;

    const int tid  = threadIdx.x;
    const int lane = tid & 31, wrp = tid >> 5;
    int bid = blockIdx.x;
    const int tzb = bid % NTZ; bid /= NTZ;
    const int tyb = bid % NTY;
    const int bp  = bid / NTY;
    const int y0 = tyb * TY, z0 = tzb * TZ;

    const int iy1 = lane / TZI, zz1 = lane - iy1 * TZI;
    const int l2  = lane + 32;
    const int iy2 = l2 / TZI,   zz2 = l2 - iy2 * TZI;
    const bool e1 = lane < WIN, e2 = l2 < WIN;
    const int soff1 = (y0 + iy1) * S + z0 + zz1;
    const int soff2 = (iy2 - iy1) * S + (zz2 - zz1);

    const int pos = tid;
    const int ow  = pos / O, ox = pos - ow * O;
    const bool active = (pos < O * O);

    u64 acc[COUT][TY][TZ];
    #pragma unroll
    for (int c = 0; c < COUT; c++) {
        float bv = bias[c];
        u64 bpk = pk2(bv, bv);
        #pragma unroll
        for (int ty = 0; ty < TY; ty++)
            #pragma unroll
            for (int tz = 0; tz < TZ; tz++) acc[c][ty][tz] = bpk;
    }

    const u64* inb = in + (size_t)bp * CIN * S4;

    for (int cin = 0; cin < CIN; cin++) {
        __syncthreads();
        for (int i = tid; i < WCH; i += BDIM) {
            int c = i / K4, r = i - c * K4;
            float w = wt[(c * CIN + cin) * K4 + r];
            sw2[r * COUT + c] = pk2(w, w);
        }
        {
            const u64* s = inb + (size_t)cin * S4 + soff1 + wrp * S2;
            u64* d = siu + iy1 * TZI + zz1 + wrp * SLAB;
            for (int p = wrp; p < S2; p += NWARP) {
                if (e1) d[0]  = s[0];
                if (e2) d[32] = s[soff2];
                s += NWARP * S2; d += NWARP * SLAB;
            }
        }
        __syncthreads();

        if (active) {
            #pragma unroll 1
            for (int kw = 0; kw < K; kw++)
            #pragma unroll 1
            for (int kx = 0; kx < K; kx++) {
                const u64* ip = siu + ((ow + kw) * S + ox + kx) * SLAB;
                u64 win[WIN];
                #pragma unroll
                for (int i = 0; i < WIN; i++) win[i] = ip[i];

                const u64* wb = sw2 + ((kw * K + kx) * K * K) * COUT;
                #pragma unroll
                for (int ky = 0; ky < K; ky++) {
                    u64 wr[K * COUT];
                    hoistw<K * COUT>(wr, wb + ky * K * COUT);
                    #pragma unroll
                    for (int ty = 0; ty < TY; ty++)
                    #pragma unroll
                    for (int kz = 0; kz < K; kz++)
                    #pragma unroll
                    for (int tz = 0; tz < TZ; tz++)
                    #pragma unroll
                    for (int c = 0; c < COUT; c++)
                        acc[c][ty][tz] = fma2(win[(ky + ty) * TZI + tz + kz],
                                              wr[kz*COUT + c], acc[c][ty][tz]);
                }
            }
        }
    }

    if (active) {
        #pragma unroll
        for (int c = 0; c < COUT; c++)
        #pragma unroll
        for (int ty = 0; ty < TY; ty++)
        #pragma unroll
        for (int tz = 0; tz < TZ; tz++) {
            size_t idx = (((((size_t)bp * COUT + c) * O + ow) * O + ox) * O
                          + (y0 + ty)) * O + (z0 + tz);
            out[idx] = relu2(acc[c][ty][tz]);
        }
    }
}

// ---------------------------------------------------------------------------
// L4: whole-spatial pair conv, W-split. FLAT staging copy (src = base + i).
// ---------------------------------------------------------------------------
template<int CIN,int COUT,int S,int K,int WSPLIT,int BDIM,int MINB>
__global__ __launch_bounds__(BDIM, MINB)
void conv4d_fullz_u(const u64* __restrict__ in, const float* __restrict__ wt,
                    const float* __restrict__ bias, u64* __restrict__ out)
{
    constexpr int O    = S - K + 1;
    constexpr int K4   = K * K * K * K;
    constexpr int OWT  = O / WSPLIT;
    constexpr int WT   = OWT + K - 1;
    static_assert(O % WSPLIT == 0 && BDIM >= OWT * O * O, "");
    constexpr int S3  = S * S * S;
    constexpr int S4  = S * S3;
    constexpr int ISZ = WT * S3;
    constexpr int WCH = COUT * K4;
    static_assert((K * COUT) % 2 == 0, "");

    extern __shared__ u64 smu[];
    u64* sw2 = smu;
    u64* siu = smu + WCH;

    const int tid = threadIdx.x;
    const int ws  = blockIdx.x % WSPLIT;
    const int bp  = blockIdx.x / WSPLIT;
    const int w0  = ws * OWT;

    const int pos = tid;
    int oy = pos % O, t0 = pos / O;
    int ox = t0 % O, owl = t0 / O;
    const bool active = (pos < OWT * O * O);

    u64 acc[COUT][O];
    #pragma unroll
    for (int c = 0; c < COUT; c++) {
        float bv = bias[c];
        u64 bpk = pk2(bv, bv);
        #pragma unroll
        for (int z = 0; z < O; z++) acc[c][z] = bpk;
    }

    const u64* inb = in + (size_t)bp * CIN * S4;

    for (int cin = 0; cin < CIN; cin++) {
        __syncthreads();
        for (int i = tid; i < WCH; i += BDIM) {
            int c = i / K4, r = i - c * K4;
            float w = wt[(c * CIN + cin) * K4 + r];
            sw2[r * COUT + c] = pk2(w, w);
        }
        {
            const u64* src = inb + (size_t)cin * S4 + w0 * S3;
            for (int i = tid; i < ISZ; i += BDIM) siu[i] = src[i];  // flat copy
        }
        __syncthreads();

        if (active) {
            #pragma unroll 1
            for (int kw = 0; kw < K; kw++)
            #pragma unroll 1
            for (int kx = 0; kx < K; kx++) {
                const u64* plane = siu + ((owl + kw) * S + ox + kx) * S * S;
                const u64* wb = sw2 + ((kw * K + kx) * K * K) * COUT;
                #pragma unroll
                for (int ky = 0; ky < K; ky++) {
                    u64 wr[K * COUT];
                    hoistw<K * COUT>(wr, wb + ky * K * COUT);
                    const u64* rowp = plane + (oy + ky) * S;
                    u64 row[S];
                    #pragma unroll
                    for (int z = 0; z < S; z++) row[z] = rowp[z];
                    #pragma unroll
                    for (int kz = 0; kz < K; kz++)
                    #pragma unroll
                    for (int z = 0; z < O; z++)
                    #pragma unroll
                    for (int c = 0; c < COUT; c++)
                        acc[c][z] = fma2(row[z + kz], wr[kz*COUT + c], acc[c][z]);
                }
            }
        }
    }

    if (active) {
        const int ow = w0 + owl;
        #pragma unroll
        for (int c = 0; c < COUT; c++)
        #pragma unroll
        for (int z = 0; z < O; z++) {
            size_t idx = (((((size_t)bp * COUT + c) * O + ow) * O + ox) * O + oy) * O + z;
            out[idx] = relu2(acc[c][z]);
        }
    }
}

// ---------------------------------------------------------------------------
// FUSED L5 + dense head. One block per batch pair. (flat staging already)
// ---------------------------------------------------------------------------
template<int CIN,int COUT,int S,int K,int BDIM>
__global__ __launch_bounds__(BDIM)
void conv5_head_u(const u64* __restrict__ in, const float* __restrict__ wt,
                  const float* __restrict__ bias,
                  const float* __restrict__ dw1, const float* __restrict__ db1,
                  const float* __restrict__ dw2, const float* __restrict__ db2,
                  float* __restrict__ out)
{
    constexpr int O    = S - K + 1;            // 4
    constexpr int K4   = K * K * K * K;
    constexpr int ISZ  = CIN * S * S * S * S;  // 6480 u64
    constexpr int WSZ  = COUT * CIN * K4;      // 2025 u64
    constexpr int FEAT = COUT * O * O * O * O; // 1280
    static_assert(BDIM >= FEAT / COUT, "");

    extern __shared__ u64 smu[];
    u64*   siu   = smu;
    u64*   sw2   = smu + ISZ;
    float* srow0 = (float*)(smu + ISZ + WSZ);
    float* srow1 = srow0 + FEAT;
    float* gbuf  = srow1 + FEAT;

    const int tid = threadIdx.x, bp = blockIdx.x;

    for (int i = tid; i < WSZ; i += BDIM) {
        int c = i / (CIN*K4); int r = i - c * (CIN*K4);
        float w = wt[i];
        sw2[r * COUT + c] = pk2(w, w);
    }
    const u64* inb = in + (size_t)bp * ISZ;
    for (int i = tid; i < ISZ; i += BDIM) siu[i] = inb[i];
    __syncthreads();

    {
        const int pos = tid;
        if (pos < O * O * O * O) {
            int oz = pos % O; int t = pos / O;
            int oy = t % O;   t /= O;
            int ox = t % O;   int ow = t / O;

            u64 acc[COUT];
            #pragma unroll
            for (int c = 0; c < COUT; c++) { float bv = bias[c]; acc[c] = pk2(bv, bv); }

            #pragma unroll 1
            for (int cin = 0; cin < CIN; cin++)
            #pragma unroll 1
            for (int kw = 0; kw < K; kw++)
            #pragma unroll 1
            for (int kx = 0; kx < K; kx++) {
                const u64* plane = siu + ((cin * S + ow + kw) * S + ox + kx) * S * S;
                #pragma unroll
                for (int ky = 0; ky < K; ky++) {
                    const u64* r  = plane + (oy + ky) * S + oz;
                    const u64* wp = sw2 + ((((cin*K + kw)*K + kx)*K + ky) * K) * COUT;
                    #pragma unroll
                    for (int kz = 0; kz < K; kz++)
                    #pragma unroll
                    for (int c = 0; c < COUT; c++)
                        acc[c] = fma2(r[kz], wp[kz * COUT + c], acc[c]);
                }
            }
            #pragma unroll
            for (int c = 0; c < COUT; c++) {
                float lo, hi; unpk2(acc[c], lo, hi);
                int fidx = c * (O*O*O*O) + pos;
                srow0[fidx] = fmaxf(lo, 0.f);
                srow1[fidx] = fmaxf(hi, 0.f);
            }
        }
    }
    __syncthreads();

    const int f = tid >> 2, p = tid & 3;
    #pragma unroll
    for (int r = 0; r < 2; r++) {
        const float* srow = r ? srow1 : srow0;
        float s = 0.f;
        if (f < 33) {
            const float* wrow = dw1 + f * FEAT;
            for (int k = p; k < FEAT; k += 4) s = fmaf(srow[k], wrow[k], s);
        }
        s += __shfl_xor_sync(0xffffffffu, s, 1);
        s += __shfl_xor_sync(0xffffffffu, s, 2);
        if (p == 0 && f < 33) gbuf[r * 33 + f] = fmaxf(s + db1[f], 0.f);
    }
    __syncthreads();

    if (tid < 2) {
        const float* g = gbuf + tid * 33;
        float l0 = db2[0], l1 = db2[1];
        #pragma unroll
        for (int j = 0; j < 33; j++) {
            l0 = fmaf(g[j], dw2[j], l0);
            l1 = fmaf(g[j], dw2[33 + j], l1);
        }
        float m  = fmaxf(l0, l1);
        float e0 = expf(l0 - m), e1 = expf(l1 - m);
        float inv = 1.f / (e0 + e1);
        out[(2*bp + tid) * 2 + 0] = e0 * inv;
        out[(2*bp + tid) * 2 + 1] = e1 * inv;
    }
}

// ---------------------------------------------------------------------------
extern "C" void kernel_launch(void* const* d_in, const int* in_sizes, int n_in,
                              void* d_out, int out_size)
{
    (void)in_sizes; (void)n_in; (void)out_size;
    const float* x   = (const float*)d_in[0];
    const float* w1  = (const float*)d_in[1];  const float* b1  = (const float*)d_in[2];
    const float* w2  = (const float*)d_in[3];  const float* b2  = (const float*)d_in[4];
    const float* w3  = (const float*)d_in[5];  const float* b3  = (const float*)d_in[6];
    const float* w4  = (const float*)d_in[7];  const float* b4  = (const float*)d_in[8];
    const float* w5  = (const float*)d_in[9];  const float* b5  = (const float*)d_in[10];
    const float* dw1 = (const float*)d_in[11]; const float* db1 = (const float*)d_in[12];
    const float* dw2 = (const float*)d_in[13]; const float* db2 = (const float*)d_in[14];
    float* out = (float*)d_out;

    void *p1, *p2, *p3, *p4;
    cudaGetSymbolAddress(&p1, g_h1);
    cudaGetSymbolAddress(&p2, g_h2);
    cudaGetSymbolAddress(&p3, g_h3);
    cudaGetSymbolAddress(&p4, g_h4);
    u64 *h1 = (u64*)p1, *h2 = (u64*)p2, *h3 = (u64*)p3, *h4 = (u64*)p4;

    constexpr int SM1 = (3*256 + 18*18*37) * 8;   // 102,048
    constexpr int SM2 = (3*256 + 15*15*35) * 8;   //  69,144
    constexpr int SM3 = (4*256 + 12*12*37) * 8;   //  50,816
    constexpr int SM4 = (5*256 + 6*9*9*9)  * 8;   //  45,232
    constexpr int SM5 = (6480 + 2025) * 8 + (2*1280 + 68) * 4;  // ~78.6 KB

    cudaFuncSetAttribute((const void*)conv4d_l1<1,3,18,4,3,3,37,256,2>,
                         cudaFuncAttributeMaxDynamicSharedMemorySize, SM1);
    cudaFuncSetAttribute((const void*)conv4d_win_u<3,3,15,4,2,4,35,160,2>,
                         cudaFuncAttributeMaxDynamicSharedMemorySize, SM2);
    cudaFuncSetAttribute((const void*)conv4d_win_u<3,4,12,4,3,3,37,96,3>,
                         cudaFuncAttributeMaxDynamicSharedMemorySize, SM3);
    cudaFuncSetAttribute((const void*)conv4d_fullz_u<4,5,9,4,2,128,3>,
                         cudaFuncAttributeMaxDynamicSharedMemorySize, SM4);
    cudaFuncSetAttribute((const void*)conv5_head_u<5,5,6,3,256>,
                         cudaFuncAttributeMaxDynamicSharedMemorySize, SM5);

    constexpr int NBP = BATCH / 2;   // 128 batch pairs

    conv4d_l1<1,3,18,4,3,3,37,256,2><<<NBP*5*5, 256, SM1>>>(x,  w1, b1, h1);
    conv4d_win_u<3,3,15,4,2,4,35,160,2><<<NBP*6*3, 160, SM2>>>(h1, w2, b2, h2);
    conv4d_win_u<3,4,12,4,3,3,37,96,3><<<NBP*3*3,  96, SM3>>>(h2, w3, b3, h3);
    conv4d_fullz_u<4,5,9,4,2,128,3><<<NBP*2, 128, SM4>>>(h3, w4, b4, h4);
    conv5_head_u<5,5,6,3,256><<<NBP, 256, SM5>>>(h4, w5, b5,
                                                 dw1, db1, dw2, db2, out);
}